// round 11
// baseline (speedup 1.0000x reference)
#include <cuda_runtime.h>
#include <math.h>

// ---------------------------------------------------------------------------
// GNNLoss fused single-kernel (R11): contiguous per-CTA streaming.
//
// R3-R10 all hit a ~3.5TB/s (45%) DRAM wall regardless of warps/regs/ILP.
// Diagnosis: grid-stride loops make every 512B warp-read jump 2.4MB ->
// one HBM row-activate per 512B -> activate-rate-limited bandwidth.
// R11 partitions the edge stream into contiguous per-CTA tiles iterated
// thread-linearly: 16KB contiguous per CTA-iteration per array, consecutive
// iterations extend the same rows.
//
// Everything else = best-known (R7): 1024thr x 1 CTA/SM, 200KB u8 hash
// filter in smem, focal(t=0) unconditional hot path (P(t=1)~6e-5), rare
// corrections behind two warp votes, exact u16 key fallback.
// ---------------------------------------------------------------------------

#define MAX_NODES  262144
#define MAX_BLOCKS 512
#define NTHREADS   1024

__device__ __align__(16) unsigned short g_keys[MAX_NODES];
__device__ __align__(16) unsigned char  g_hash[MAX_NODES];
__device__ float g_part_es[MAX_BLOCKS];
__device__ int   g_part_ec[MAX_BLOCKS];
__device__ float g_part_ns[MAX_BLOCKS];
__device__ int   g_part_nc[MAX_BLOCKS];
__device__ unsigned int g_bar0;   // zero-init; reset by block 0 each run
__device__ unsigned int g_bar1;

__device__ __forceinline__ float rcp_approx(float x) {
    float y;
    asm("rcp.approx.f32 %0, %1;" : "=f"(y) : "f"(x));
    return y;
}

// generic focal term (node phase / tail only)
__device__ __forceinline__ float focal_term(float x, bool t) {
    float a  = fabsf(x);
    float em = __expf(-a);
    float w  = 1.0f + em;
    float L  = __logf(w);
    float q  = em * rcp_approx(w);
    bool  m  = ((x >= 0.0f) == t);
    float omp = m ? q : (1.0f - q);
    float ce  = m ? L : (a + L);
    float at  = t ? 0.25f : 0.75f;
    return at * ce * omp * omp;
}

// hot-path focal with t = 0 hard-coded
__device__ __forceinline__ float focal_t0(float x) {
    float a  = fabsf(x);
    float em = __expf(-a);
    float w  = 1.0f + em;
    float L  = __logf(w);
    float q  = em * rcp_approx(w);
    bool  neg = (x < 0.0f);
    float omp = neg ? q : (1.0f - q);
    float ce  = neg ? L : (a + L);
    return 0.75f * ce * omp * omp;
}

// rare correction: loss(x,1) - loss(x,0)   (cold path, recomputed)
__device__ __forceinline__ float focal_delta(float x) {
    float a  = fabsf(x);
    float em = __expf(-a);
    float w  = 1.0f + em;
    float L  = __logf(w);
    float q  = em * rcp_approx(w);
    bool  pos = (x >= 0.0f);
    float omp1 = pos ? q : (1.0f - q);
    float ce1  = pos ? L : (a + L);
    float omp0 = pos ? (1.0f - q) : q;
    float ce0  = pos ? (a + L) : L;
    return 0.25f * ce1 * omp1 * omp1 - 0.75f * ce0 * omp0 * omp0;
}

__device__ __forceinline__ void block_reduce_store(float s, int c,
                                                   float* ps, int* pc) {
    #pragma unroll
    for (int o = 16; o > 0; o >>= 1) {
        s += __shfl_down_sync(0xFFFFFFFFu, s, o);
        c += __shfl_down_sync(0xFFFFFFFFu, c, o);
    }
    __shared__ float sh_s[32];
    __shared__ int   sh_c[32];
    int lane = threadIdx.x & 31;
    int wid  = threadIdx.x >> 5;
    if (lane == 0) { sh_s[wid] = s; sh_c[wid] = c; }
    __syncthreads();
    int nw = (blockDim.x + 31) >> 5;
    if (wid == 0) {
        s = (lane < nw) ? sh_s[lane] : 0.0f;
        c = (lane < nw) ? sh_c[lane] : 0;
        #pragma unroll
        for (int o = 16; o > 0; o >>= 1) {
            s += __shfl_down_sync(0xFFFFFFFFu, s, o);
            c += __shfl_down_sync(0xFFFFFFFFu, c, o);
        }
        if (lane == 0) { ps[blockIdx.x] = s; pc[blockIdx.x] = c; }
    }
    __syncthreads();
}

__device__ __forceinline__ void grid_barrier(unsigned int* bar, int nb) {
    __syncthreads();
    if (threadIdx.x == 0) {
        __threadfence();
        atomicAdd(bar, 1u);
        while (*(volatile unsigned int*)bar < (unsigned int)nb) { }
    }
    __syncthreads();
    __threadfence();
}

__global__ void __launch_bounds__(NTHREADS, 1)
fused_kernel(const float* __restrict__ edge_logits,
             const float* __restrict__ node_logits,
             const int*   __restrict__ batch,
             const int*   __restrict__ pinst,
             const int*   __restrict__ src,
             const int*   __restrict__ dst,
             int E, int N, int nvec,
             float* __restrict__ out) {
    extern __shared__ unsigned char sh[];
    int tid = threadIdx.x;
    int nb  = gridDim.x;

    // ---- phase 1: nodes, contiguous per-CTA tile ----
    float ns = 0.0f; int nc = 0;
    {
        int chunk = (N + nb - 1) / nb;
        int beg = blockIdx.x * chunk;
        int end = beg + chunk; if (end > N) end = N;
        for (int i = beg + tid; i < end; i += NTHREADS) {
            int p = pinst[i];
            int b = batch[i];
            unsigned short key = (p == 0) ? (unsigned short)0
                                          : (unsigned short)((b << 10) | p);
            g_keys[i] = key;
            g_hash[i] = (key == 0) ? (unsigned char)0
                                   : (unsigned char)((key % 255) + 1);
            float x = node_logits[i];
            bool  t = (p != 0);
            ns += focal_term(x, t);
            nc += ((x > 0.0f) == t) ? 1 : 0;
        }
    }
    block_reduce_store(ns, nc, g_part_ns, g_part_nc);

    grid_barrier(&g_bar0, nb);   // tables complete, visible in L2

    // ---- broadcast hash table into shared memory ----
    int nw4 = (N + 15) >> 4;
    const uint4* hv = (const uint4*)g_hash;
    uint4* s4 = (uint4*)sh;
    for (int i = tid; i < nw4; i += NTHREADS) s4[i] = hv[i];
    __syncthreads();

    // ---- phase 2: edges, contiguous per-CTA tile (row-friendly) ----
    const float4* elv = (const float4*)edge_logits;
    const int4*   svp = (const int4*)src;
    const int4*   dvp = (const int4*)dst;
    float es = 0.0f; int ec = 0;

    {
        int chunk = (nvec + nb - 1) / nb;
        int beg = blockIdx.x * chunk;
        int end = beg + chunk; if (end > nvec) end = nvec;
        for (int i = beg + tid; i < end; i += NTHREADS) {
            float4 x  = __ldcs(&elv[i]);
            int4   sv = __ldcs(&svp[i]);
            int4   dv = __ldcs(&dvp[i]);

            // hash filter (smem gathers)
            unsigned int h0s = sh[sv.x], h0d = sh[dv.x];
            unsigned int h1s = sh[sv.y], h1d = sh[dv.y];
            unsigned int h2s = sh[sv.z], h2d = sh[dv.z];
            unsigned int h3s = sh[sv.w], h3d = sh[dv.w];
            bool n0 = (h0s == h0d) & (h0s != 0u);
            bool n1 = (h1s == h1d) & (h1s != 0u);
            bool n2 = (h2s == h2d) & (h2s != 0u);
            bool n3 = (h3s == h3d) & (h3s != 0u);

            // unconditional t=0 loss + accuracy (depends only on x)
            es += focal_t0(x.x);
            es += focal_t0(x.y);
            es += focal_t0(x.z);
            es += focal_t0(x.w);
            ec += (x.x <= 0.0f) ? 1 : 0;
            ec += (x.y <= 0.0f) ? 1 : 0;
            ec += (x.z <= 0.0f) ? 1 : 0;
            ec += (x.w <= 0.0f) ? 1 : 0;

            // rare corrections behind two warp votes
            unsigned int amask = __activemask();
            if (__any_sync(amask, n0 | n1 | n2 | n3)) {
                bool t0 = n0 && (__ldg(&g_keys[sv.x]) == __ldg(&g_keys[dv.x]));
                bool t1 = n1 && (__ldg(&g_keys[sv.y]) == __ldg(&g_keys[dv.y]));
                bool t2 = n2 && (__ldg(&g_keys[sv.z]) == __ldg(&g_keys[dv.z]));
                bool t3 = n3 && (__ldg(&g_keys[sv.w]) == __ldg(&g_keys[dv.w]));
                if (__any_sync(amask, t0 | t1 | t2 | t3)) {
                    if (t0) { es += focal_delta(x.x); ec += (x.x > 0.0f) ? 1 : -1; }
                    if (t1) { es += focal_delta(x.y); ec += (x.y > 0.0f) ? 1 : -1; }
                    if (t2) { es += focal_delta(x.z); ec += (x.z > 0.0f) ? 1 : -1; }
                    if (t3) { es += focal_delta(x.w); ec += (x.w > 0.0f) ? 1 : -1; }
                }
            }
        }
    }

    // tail edges (E % 4, or whole range if vec path disabled)
    if (blockIdx.x == 0 && tid == 0) {
        for (int e = nvec << 2; e < E; e++) {
            int sidx = src[e], didx = dst[e];
            unsigned short ks = g_keys[sidx], kd = g_keys[didx];
            bool t = (ks == kd) && (ks != 0);
            float xe = edge_logits[e];
            es += focal_term(xe, t);
            ec += ((xe > 0.0f) == t) ? 1 : 0;
        }
    }
    block_reduce_store(es, ec, g_part_es, g_part_ec);

    // ---- final barrier; block 0 reduces partials and writes outputs ----
    if (tid == 0) { __threadfence(); atomicAdd(&g_bar1, 1u); }
    if (blockIdx.x != 0) return;
    if (tid == 0) {
        while (*(volatile unsigned int*)&g_bar1 < (unsigned int)nb) { }
    }
    __syncthreads();
    __threadfence();

    if (tid < 32) {
        double des = 0.0, dns = 0.0;
        int iec = 0, inc = 0;
        for (int k = tid; k < nb; k += 32) {
            des += (double)g_part_es[k];
            dns += (double)g_part_ns[k];
            iec += g_part_ec[k];
            inc += g_part_nc[k];
        }
        #pragma unroll
        for (int o = 16; o > 0; o >>= 1) {
            des += __shfl_down_sync(0xFFFFFFFFu, des, o);
            dns += __shfl_down_sync(0xFFFFFFFFu, dns, o);
            iec += __shfl_down_sync(0xFFFFFFFFu, iec, o);
            inc += __shfl_down_sync(0xFFFFFFFFu, inc, o);
        }
        if (tid == 0) {
            float edge_loss = (float)(des / (double)E);
            float node_loss = (float)(dns / (double)N);
            out[0] = edge_loss + node_loss;  // EDGE_W = NODE_W = 1
            out[1] = edge_loss;
            out[2] = node_loss;
            out[3] = (float)((double)iec / (double)E);
            out[4] = (float)((double)inc / (double)N);
            g_bar0 = 0;                      // reset for next graph replay
            g_bar1 = 0;
        }
    }
}

extern "C" void kernel_launch(void* const* d_in, const int* in_sizes, int n_in,
                              void* d_out, int out_size) {
    const float* edge_logits = (const float*)d_in[0];
    const float* node_logits = (const float*)d_in[1];
    const int*   batch       = (const int*)d_in[2];
    const int*   pinst       = (const int*)d_in[3];
    const int*   edge_index  = (const int*)d_in[4];

    int E = in_sizes[0];
    int N = in_sizes[1];
    const int* src = edge_index;
    const int* dst = edge_index + E;
    float* out = (float*)d_out;

    int nvec = ((E & 3) == 0) ? (E >> 2) : 0;

    int smem_bytes = ((N + 15) >> 4) << 4;   // 8-bit hash table, 200KB
    cudaFuncSetAttribute(fused_kernel,
                         cudaFuncAttributeMaxDynamicSharedMemorySize,
                         smem_bytes);

    int sm_count = 148;
    cudaDeviceGetAttribute(&sm_count, cudaDevAttrMultiProcessorCount, 0);

    // size the grid by ACTUAL occupancy so the grid barrier cannot deadlock
    int per_sm = 1;
    cudaOccupancyMaxActiveBlocksPerMultiprocessor(&per_sm, fused_kernel,
                                                  NTHREADS, smem_bytes);
    if (per_sm < 1) per_sm = 1;
    int nblocks = sm_count * per_sm;
    if (nblocks > MAX_BLOCKS) nblocks = MAX_BLOCKS;

    fused_kernel<<<nblocks, NTHREADS, smem_bytes>>>(edge_logits, node_logits,
                                                    batch, pinst, src, dst,
                                                    E, N, nvec, out);
}

// round 12
// speedup vs baseline: 1.0013x; 1.0013x over previous
#include <cuda_runtime.h>
#include <math.h>

// ---------------------------------------------------------------------------
// GNNLoss fused single-kernel (R12): pipe decomposition.
//
// R3-R11: every variant (warps/regs/ILP/access-pattern sweep) hit ~3.5TB/s.
// Invariant: streams (LDG.128) and divergent byte-LDS gathers interleaved in
// the same warps -> unified L1/LSU interference. R12 separates them:
//   Pass A: pure logit stream + focal(t=0) math, ZERO LDS. (before barrier)
//   Pass B: index streams + smem hash filter + votes; NO logit stream, NO
//           focal math; true matches (~790 of 12.8M edges) load their logit
//           scalar and apply delta corrections.
//
// key[node]  = (pi==0) ? 0 : (batch<<10)|pi     (u16 exact)
// hash[node] = (key==0) ? 0 : (key % 255) + 1   (u8 filter, 200KB smem)
// ---------------------------------------------------------------------------

#define MAX_NODES  262144
#define MAX_BLOCKS 512
#define NTHREADS   1024

__device__ __align__(16) unsigned short g_keys[MAX_NODES];
__device__ __align__(16) unsigned char  g_hash[MAX_NODES];
__device__ float g_part_es[MAX_BLOCKS];
__device__ int   g_part_ec[MAX_BLOCKS];
__device__ float g_part_ns[MAX_BLOCKS];
__device__ int   g_part_nc[MAX_BLOCKS];
__device__ unsigned int g_bar0;   // zero-init; reset by block 0 each run
__device__ unsigned int g_bar1;

__device__ __forceinline__ float rcp_approx(float x) {
    float y;
    asm("rcp.approx.f32 %0, %1;" : "=f"(y) : "f"(x));
    return y;
}

// generic focal term (node phase / tail only)
__device__ __forceinline__ float focal_term(float x, bool t) {
    float a  = fabsf(x);
    float em = __expf(-a);
    float w  = 1.0f + em;
    float L  = __logf(w);
    float q  = em * rcp_approx(w);
    bool  m  = ((x >= 0.0f) == t);
    float omp = m ? q : (1.0f - q);
    float ce  = m ? L : (a + L);
    float at  = t ? 0.25f : 0.75f;
    return at * ce * omp * omp;
}

// hot-path focal with t = 0 hard-coded
__device__ __forceinline__ float focal_t0(float x) {
    float a  = fabsf(x);
    float em = __expf(-a);
    float w  = 1.0f + em;
    float L  = __logf(w);
    float q  = em * rcp_approx(w);
    bool  neg = (x < 0.0f);
    float omp = neg ? q : (1.0f - q);
    float ce  = neg ? L : (a + L);
    return 0.75f * ce * omp * omp;
}

// rare correction: loss(x,1) - loss(x,0)
__device__ __forceinline__ float focal_delta(float x) {
    float a  = fabsf(x);
    float em = __expf(-a);
    float w  = 1.0f + em;
    float L  = __logf(w);
    float q  = em * rcp_approx(w);
    bool  pos = (x >= 0.0f);
    float omp1 = pos ? q : (1.0f - q);
    float ce1  = pos ? L : (a + L);
    float omp0 = pos ? (1.0f - q) : q;
    float ce0  = pos ? (a + L) : L;
    return 0.25f * ce1 * omp1 * omp1 - 0.75f * ce0 * omp0 * omp0;
}

__device__ __forceinline__ void block_reduce_store(float s, int c,
                                                   float* ps, int* pc) {
    #pragma unroll
    for (int o = 16; o > 0; o >>= 1) {
        s += __shfl_down_sync(0xFFFFFFFFu, s, o);
        c += __shfl_down_sync(0xFFFFFFFFu, c, o);
    }
    __shared__ float sh_s[32];
    __shared__ int   sh_c[32];
    int lane = threadIdx.x & 31;
    int wid  = threadIdx.x >> 5;
    if (lane == 0) { sh_s[wid] = s; sh_c[wid] = c; }
    __syncthreads();
    int nw = (blockDim.x + 31) >> 5;
    if (wid == 0) {
        s = (lane < nw) ? sh_s[lane] : 0.0f;
        c = (lane < nw) ? sh_c[lane] : 0;
        #pragma unroll
        for (int o = 16; o > 0; o >>= 1) {
            s += __shfl_down_sync(0xFFFFFFFFu, s, o);
            c += __shfl_down_sync(0xFFFFFFFFu, c, o);
        }
        if (lane == 0) { ps[blockIdx.x] = s; pc[blockIdx.x] = c; }
    }
    __syncthreads();
}

__device__ __forceinline__ void grid_barrier(unsigned int* bar, int nb) {
    __syncthreads();
    if (threadIdx.x == 0) {
        __threadfence();
        atomicAdd(bar, 1u);
        while (*(volatile unsigned int*)bar < (unsigned int)nb) { }
    }
    __syncthreads();
    __threadfence();
}

__global__ void __launch_bounds__(NTHREADS, 1)
fused_kernel(const float* __restrict__ edge_logits,
             const float* __restrict__ node_logits,
             const int*   __restrict__ batch,
             const int*   __restrict__ pinst,
             const int*   __restrict__ src,
             const int*   __restrict__ dst,
             int E, int N, int nvec,
             float* __restrict__ out) {
    extern __shared__ unsigned char sh[];
    int tid     = threadIdx.x;
    int nb      = gridDim.x;
    int gtid    = blockIdx.x * blockDim.x + tid;
    int gstride = nb * blockDim.x;

    // ---- phase 1: nodes (build key + hash tables, node loss/acc) ----
    float ns = 0.0f; int nc = 0;
    for (int i = gtid; i < N; i += gstride) {
        int p = pinst[i];
        int b = batch[i];
        unsigned short key = (p == 0) ? (unsigned short)0
                                      : (unsigned short)((b << 10) | p);
        g_keys[i] = key;
        g_hash[i] = (key == 0) ? (unsigned char)0
                               : (unsigned char)((key % 255) + 1);
        float x = node_logits[i];
        bool  t = (p != 0);
        ns += focal_term(x, t);
        nc += ((x > 0.0f) == t) ? 1 : 0;
    }
    block_reduce_store(ns, nc, g_part_ns, g_part_nc);

    // ---- pass A: PURE logit stream, focal(t=0) for every edge ----
    // (no LDS, no gathers; deep MLP via 2x float4 unroll; before barrier)
    float es = 0.0f; int ec = 0;
    {
        const float4* elv = (const float4*)edge_logits;
        for (int i = gtid; i < nvec; i += 2 * gstride) {
            int j = i + gstride;
            float4 xa = __ldcs(&elv[i]);
            float4 xb;
            bool vj = (j < nvec);
            if (vj) xb = __ldcs(&elv[j]);

            es += focal_t0(xa.x) + focal_t0(xa.y)
                + focal_t0(xa.z) + focal_t0(xa.w);
            ec += ((xa.x <= 0.0f) ? 1 : 0) + ((xa.y <= 0.0f) ? 1 : 0)
                + ((xa.z <= 0.0f) ? 1 : 0) + ((xa.w <= 0.0f) ? 1 : 0);
            if (vj) {
                es += focal_t0(xb.x) + focal_t0(xb.y)
                    + focal_t0(xb.z) + focal_t0(xb.w);
                ec += ((xb.x <= 0.0f) ? 1 : 0) + ((xb.y <= 0.0f) ? 1 : 0)
                    + ((xb.z <= 0.0f) ? 1 : 0) + ((xb.w <= 0.0f) ? 1 : 0);
            }
        }
    }

    grid_barrier(&g_bar0, nb);   // key/hash tables complete, visible in L2

    // ---- broadcast hash table into shared memory ----
    int nw4 = (N + 15) >> 4;
    const uint4* hv = (const uint4*)g_hash;
    uint4* s4 = (uint4*)sh;
    for (int i = tid; i < nw4; i += NTHREADS) s4[i] = hv[i];
    __syncthreads();

    // ---- pass B: index streams + gathers; corrections only ----
    {
        const int4* svp = (const int4*)src;
        const int4* dvp = (const int4*)dst;
        for (int i = gtid; i < nvec; i += 2 * gstride) {
            int j = i + gstride;
            bool vj = (j < nvec);

            int4 sva = __ldcs(&svp[i]);
            int4 dva = __ldcs(&dvp[i]);
            int4 svb, dvb;
            if (vj) { svb = __ldcs(&svp[j]); dvb = __ldcs(&dvp[j]); }

            // chunk A filter
            unsigned int a0s = sh[sva.x], a0d = sh[dva.x];
            unsigned int a1s = sh[sva.y], a1d = sh[dva.y];
            unsigned int a2s = sh[sva.z], a2d = sh[dva.z];
            unsigned int a3s = sh[sva.w], a3d = sh[dva.w];
            bool na0 = (a0s == a0d) & (a0s != 0u);
            bool na1 = (a1s == a1d) & (a1s != 0u);
            bool na2 = (a2s == a2d) & (a2s != 0u);
            bool na3 = (a3s == a3d) & (a3s != 0u);

            bool nb0 = false, nb1 = false, nb2 = false, nb3 = false;
            if (vj) {
                unsigned int b0s = sh[svb.x], b0d = sh[dvb.x];
                unsigned int b1s = sh[svb.y], b1d = sh[dvb.y];
                unsigned int b2s = sh[svb.z], b2d = sh[dvb.z];
                unsigned int b3s = sh[svb.w], b3d = sh[dvb.w];
                nb0 = (b0s == b0d) & (b0s != 0u);
                nb1 = (b1s == b1d) & (b1s != 0u);
                nb2 = (b2s == b2d) & (b2s != 0u);
                nb3 = (b3s == b3d) & (b3s != 0u);
            }

            unsigned int amask = __activemask();
            bool anyn = na0 | na1 | na2 | na3 | nb0 | nb1 | nb2 | nb3;
            if (__any_sync(amask, anyn)) {
                bool ta0 = na0 && (__ldg(&g_keys[sva.x]) == __ldg(&g_keys[dva.x]));
                bool ta1 = na1 && (__ldg(&g_keys[sva.y]) == __ldg(&g_keys[dva.y]));
                bool ta2 = na2 && (__ldg(&g_keys[sva.z]) == __ldg(&g_keys[dva.z]));
                bool ta3 = na3 && (__ldg(&g_keys[sva.w]) == __ldg(&g_keys[dva.w]));
                bool tb0 = nb0 && (__ldg(&g_keys[svb.x]) == __ldg(&g_keys[dvb.x]));
                bool tb1 = nb1 && (__ldg(&g_keys[svb.y]) == __ldg(&g_keys[dvb.y]));
                bool tb2 = nb2 && (__ldg(&g_keys[svb.z]) == __ldg(&g_keys[dvb.z]));
                bool tb3 = nb3 && (__ldg(&g_keys[svb.w]) == __ldg(&g_keys[dvb.w]));
                bool anyt = ta0 | ta1 | ta2 | ta3 | tb0 | tb1 | tb2 | tb3;
                if (__any_sync(amask, anyt)) {   // ~790 edges total: cold
                    if (ta0) { float x = __ldg(&edge_logits[4*i+0]); es += focal_delta(x); ec += (x > 0.0f) ? 1 : -1; }
                    if (ta1) { float x = __ldg(&edge_logits[4*i+1]); es += focal_delta(x); ec += (x > 0.0f) ? 1 : -1; }
                    if (ta2) { float x = __ldg(&edge_logits[4*i+2]); es += focal_delta(x); ec += (x > 0.0f) ? 1 : -1; }
                    if (ta3) { float x = __ldg(&edge_logits[4*i+3]); es += focal_delta(x); ec += (x > 0.0f) ? 1 : -1; }
                    if (tb0) { float x = __ldg(&edge_logits[4*j+0]); es += focal_delta(x); ec += (x > 0.0f) ? 1 : -1; }
                    if (tb1) { float x = __ldg(&edge_logits[4*j+1]); es += focal_delta(x); ec += (x > 0.0f) ? 1 : -1; }
                    if (tb2) { float x = __ldg(&edge_logits[4*j+2]); es += focal_delta(x); ec += (x > 0.0f) ? 1 : -1; }
                    if (tb3) { float x = __ldg(&edge_logits[4*j+3]); es += focal_delta(x); ec += (x > 0.0f) ? 1 : -1; }
                }
            }
        }
    }

    // tail edges (E % 4, or whole range if vec path disabled)
    if (blockIdx.x == 0 && tid == 0) {
        for (int e = nvec << 2; e < E; e++) {
            int sidx = src[e], didx = dst[e];
            unsigned short ks = g_keys[sidx], kd = g_keys[didx];
            bool t = (ks == kd) && (ks != 0);
            float xe = edge_logits[e];
            es += focal_term(xe, t);
            ec += ((xe > 0.0f) == t) ? 1 : 0;
        }
    }
    block_reduce_store(es, ec, g_part_es, g_part_ec);

    // ---- final barrier; block 0 reduces partials and writes outputs ----
    if (tid == 0) { __threadfence(); atomicAdd(&g_bar1, 1u); }
    if (blockIdx.x != 0) return;
    if (tid == 0) {
        while (*(volatile unsigned int*)&g_bar1 < (unsigned int)nb) { }
    }
    __syncthreads();
    __threadfence();

    if (tid < 32) {
        double des = 0.0, dns = 0.0;
        int iec = 0, inc = 0;
        for (int k = tid; k < nb; k += 32) {
            des += (double)g_part_es[k];
            dns += (double)g_part_ns[k];
            iec += g_part_ec[k];
            inc += g_part_nc[k];
        }
        #pragma unroll
        for (int o = 16; o > 0; o >>= 1) {
            des += __shfl_down_sync(0xFFFFFFFFu, des, o);
            dns += __shfl_down_sync(0xFFFFFFFFu, dns, o);
            iec += __shfl_down_sync(0xFFFFFFFFu, iec, o);
            inc += __shfl_down_sync(0xFFFFFFFFu, inc, o);
        }
        if (tid == 0) {
            float edge_loss = (float)(des / (double)E);
            float node_loss = (float)(dns / (double)N);
            out[0] = edge_loss + node_loss;  // EDGE_W = NODE_W = 1
            out[1] = edge_loss;
            out[2] = node_loss;
            out[3] = (float)((double)iec / (double)E);
            out[4] = (float)((double)inc / (double)N);
            g_bar0 = 0;                      // reset for next graph replay
            g_bar1 = 0;
        }
    }
}

extern "C" void kernel_launch(void* const* d_in, const int* in_sizes, int n_in,
                              void* d_out, int out_size) {
    const float* edge_logits = (const float*)d_in[0];
    const float* node_logits = (const float*)d_in[1];
    const int*   batch       = (const int*)d_in[2];
    const int*   pinst       = (const int*)d_in[3];
    const int*   edge_index  = (const int*)d_in[4];

    int E = in_sizes[0];
    int N = in_sizes[1];
    const int* src = edge_index;
    const int* dst = edge_index + E;
    float* out = (float*)d_out;

    int nvec = ((E & 3) == 0) ? (E >> 2) : 0;

    int smem_bytes = ((N + 15) >> 4) << 4;   // 8-bit hash table, 200KB
    cudaFuncSetAttribute(fused_kernel,
                         cudaFuncAttributeMaxDynamicSharedMemorySize,
                         smem_bytes);

    int sm_count = 148;
    cudaDeviceGetAttribute(&sm_count, cudaDevAttrMultiProcessorCount, 0);

    // size the grid by ACTUAL occupancy so the grid barrier cannot deadlock
    int per_sm = 1;
    cudaOccupancyMaxActiveBlocksPerMultiprocessor(&per_sm, fused_kernel,
                                                  NTHREADS, smem_bytes);
    if (per_sm < 1) per_sm = 1;
    int nblocks = sm_count * per_sm;
    if (nblocks > MAX_BLOCKS) nblocks = MAX_BLOCKS;

    fused_kernel<<<nblocks, NTHREADS, smem_bytes>>>(edge_logits, node_logits,
                                                    batch, pinst, src, dst,
                                                    E, N, nvec, out);
}